// round 13
// baseline (speedup 1.0000x reference)
#include <cuda_runtime.h>
#include <math.h>
#include <stdint.h>

#define DIM 16
#define NA 131072
#define NB 1048576
#define NANG 2097152
#define NGRAPH 256
#define PI_F 3.14159274101257324219f   // fl32(pi)
#define CUTOFF_F 5.0f

// ---------------- scratch (static device globals; no runtime alloc) ----------
// Invariant: g_nd and g_pool are all-zero at entry; restored before exit.
__device__ float g_h_atm[NA * DIM];
__device__ float g_h_bnd[NB * DIM];
__device__ float g_h_ang[NANG * DIM];
__device__ float g_nd[NB * 32];       // per node: [num(16) | den(16)] = one 128B line
__device__ float g_pool[NGRAPH * DIM];
__device__ int   g_mask_mode;         // 1 = mask serialized as int32, 0 = as bytes

// ---------------- conv parameters in constant memory --------------------------
__constant__ float c_cw[3 * 2 * 5 * 256];      // conv_W  [c][g][5][16][16]
__constant__ float c_cb[3 * 2 * 2 * 16];       // conv_b  [c][g][2][16]
__constant__ float c_cln[3 * 2 * 2 * 2 * 16];  // conv_ln [c][g][2][2][16]
// angle-encoder params (enc sets 2=basic, 3=dihedral)
__constant__ float c_ew1[2 * 256];
__constant__ float c_ew2[2 * 256];
__constant__ float c_eb1[2 * 16];
__constant__ float c_eb2[2 * 16];
__constant__ float c_elg[2 * 16];
__constant__ float c_elb[2 * 16];

// ---------------- fast activations ---------------------------------------------
__device__ __forceinline__ float sigmoid_f(float x) {
    return __fdividef(1.0f, 1.0f + __expf(-x));
}
__device__ __forceinline__ float silu_f(float x) { return x * sigmoid_f(x); }

// ---------------- accurate sinf (FMA Cody-Waite) -------------------------------
__device__ __forceinline__ float sinf_cw(float x) {
    float k = rintf(__fmul_rn(x, 0.636619772367581343f));
    float r = fmaf(k, -1.57079637050628662109375f, x);
    r = fmaf(k, 4.37113900018624283e-8f, r);
    int q = ((int)k) & 3;
    float s = __fmul_rn(r, r);
    float ps = 2.75573192239859e-6f;
    ps = fmaf(ps, s, -1.98412698412698e-4f);
    ps = fmaf(ps, s, 8.33333333333333e-3f);
    ps = fmaf(ps, s, -1.66666666666667e-1f);
    float sinr = fmaf(__fmul_rn(r, s), ps, r);
    float pc = 2.48015873015873e-5f;
    pc = fmaf(pc, s, -1.38888888888889e-3f);
    pc = fmaf(pc, s, 4.16666666666667e-2f);
    pc = fmaf(pc, s, -5.0e-1f);
    float cosr = fmaf(s, pc, 1.0f);
    float v = (q & 1) ? cosr : sinr;
    return (q & 2) ? -v : v;
}

// ---------------- misc helpers -------------------------------------------------
__device__ __forceinline__ void red_add_v4(float* p, float a, float b, float c, float d) {
    asm volatile("red.global.add.v4.f32 [%0], {%1,%2,%3,%4};"
                 :: "l"(p), "f"(a), "f"(b), "f"(c), "f"(d) : "memory");
}
__device__ __forceinline__ void load16(float* r, const float* p) {
#pragma unroll
    for (int i = 0; i < 4; i++) {
        float4 v = ((const float4*)p)[i];
        r[4 * i + 0] = v.x; r[4 * i + 1] = v.y; r[4 * i + 2] = v.z; r[4 * i + 3] = v.w;
    }
}
__device__ __forceinline__ void load16_cs(float* r, const float* p) {
#pragma unroll
    for (int i = 0; i < 4; i++) {
        float4 v = __ldcs((const float4*)p + i);
        r[4 * i + 0] = v.x; r[4 * i + 1] = v.y; r[4 * i + 2] = v.z; r[4 * i + 3] = v.w;
    }
}
__device__ __forceinline__ void store16(float* p, const float* r) {
#pragma unroll
    for (int i = 0; i < 4; i++)
        ((float4*)p)[i] = make_float4(r[4 * i + 0], r[4 * i + 1], r[4 * i + 2], r[4 * i + 3]);
}
__device__ __forceinline__ void store16_cs(float* p, const float* r) {
#pragma unroll
    for (int i = 0; i < 4; i++)
        __stcs((float4*)p + i, make_float4(r[4 * i + 0], r[4 * i + 1], r[4 * i + 2], r[4 * i + 3]));
}

__device__ __forceinline__ void layernorm16(float* v, const float* g, const float* b) {
    float mu = 0.f;
#pragma unroll
    for (int j = 0; j < DIM; j++) mu += v[j];
    mu *= 0.0625f;
    float var = 0.f;
#pragma unroll
    for (int j = 0; j < DIM; j++) { float d0 = v[j] - mu; var = fmaf(d0, d0, var); }
    var *= 0.0625f;
    float r = __frsqrt_rn(var + 1e-5f);
#pragma unroll
    for (int j = 0; j < DIM; j++) v[j] = fmaf((v[j] - mu) * r, g[j], b[j]);
}

__device__ __forceinline__ void embed_16(const float* feat, float* out,
                                         const float* sW1, const float* sb1,
                                         const float* sW2, const float* sb2,
                                         const float* sg, const float* sb) {
    float h[DIM], o[DIM];
#pragma unroll
    for (int j = 0; j < DIM; j++) h[j] = sb1[j];
#pragma unroll
    for (int k = 0; k < DIM; k++) {
        float a = feat[k];
#pragma unroll
        for (int j = 0; j < DIM; j++) h[j] = fmaf(a, sW1[k * DIM + j], h[j]);
    }
#pragma unroll
    for (int j = 0; j < DIM; j++) h[j] = silu_f(h[j]);
#pragma unroll
    for (int j = 0; j < DIM; j++) o[j] = sb2[j];
#pragma unroll
    for (int k = 0; k < DIM; k++) {
        float a = h[k];
#pragma unroll
        for (int j = 0; j < DIM; j++) o[j] = fmaf(a, sW2[k * DIM + j], o[j]);
    }
    layernorm16(o, sg, sb);
#pragma unroll
    for (int j = 0; j < DIM; j++) out[j] = o[j];
}

// ---------------- mask-layout detection ----------------------------------------
__global__ void k_detect_mask(const unsigned char* __restrict__ m) {
    __shared__ int s_nz;
    if (threadIdx.x == 0) s_nz = 0;
    __syncthreads();
    int nz = 0;
    for (int i = threadIdx.x; i < 65536; i += blockDim.x)
        if ((i & 3) && m[i]) nz = 1;
    if (nz) atomicOr(&s_nz, 1);
    __syncthreads();
    if (threadIdx.x == 0) g_mask_mode = s_nz ? 0 : 1;
}

// ---------------- fused encoder: atoms (+table) and bonds ----------------------
#define ATM_BLOCKS (NA / 256)
#define BND_BLOCKS (NB / 256)
__global__ void k_enc_nb(const int* __restrict__ species, const float* __restrict__ xb,
                         const float* __restrict__ eW1, const float* __restrict__ eb1,
                         const float* __restrict__ eW2, const float* __restrict__ eb2,
                         const float* __restrict__ eg, const float* __restrict__ ebb) {
    int b = blockIdx.x;
    int t = threadIdx.x;
    if (b < ATM_BLOCKS) {
        __shared__ float s_tab[10 * DIM];
        if (t < 10) {
            int s = t;
            float h[DIM], o[DIM];
#pragma unroll
            for (int d = 0; d < DIM; d++) h[d] = silu_f(eW1[s * DIM + d] + eb1[d]);
#pragma unroll
            for (int j = 0; j < DIM; j++) o[j] = eb2[j];
#pragma unroll
            for (int k = 0; k < DIM; k++) {
                float a = h[k];
#pragma unroll
                for (int j = 0; j < DIM; j++) o[j] = fmaf(a, eW2[k * DIM + j], o[j]);
            }
            float g[DIM], bb2[DIM];
#pragma unroll
            for (int j = 0; j < DIM; j++) { g[j] = eg[j]; bb2[j] = ebb[j]; }
            layernorm16(o, g, bb2);
#pragma unroll
            for (int j = 0; j < DIM; j++) s_tab[s * DIM + j] = o[j];
        }
        __syncthreads();
        int i = b * 256 + t;
        int s = species[i];
        float4* dst = (float4*)(g_h_atm + (size_t)i * DIM);
        const float4* srcp = (const float4*)(s_tab + s * DIM);
#pragma unroll
        for (int q = 0; q < 4; q++) dst[q] = srcp[q];
    } else {
        __shared__ float sW1[256], sW2[256], sb1[16], sb2[16], sg[16], sb[16];
        for (int i = t; i < 256; i += blockDim.x) {
            sW1[i] = eW1[256 + i];
            sW2[i] = eW2[256 + i];
        }
        if (t < 16) {
            sb1[t] = eb1[16 + t]; sb2[t] = eb2[16 + t];
            sg[t] = eg[16 + t];   sb[t] = ebb[16 + t];
        }
        __syncthreads();
        int i = (b - ATM_BLOCKS) * 256 + t;
        float xx = xb[i] + 1e-5f;
        float c0 = __fdividef(0.6324555320336759f, xx);
        float feat[DIM];
#pragma unroll
        for (int j = 0; j < DIM; j++) {
            float arg = __fmul_rn(__fmul_rn((float)(j + 1), PI_F), xx) * 0.2f;
            feat[j] = c0 * sinf_cw(arg);
        }
        float out[DIM];
        embed_16(feat, out, sW1, sb1, sW2, sb2, sg, sb);
        store16_cs(g_h_bnd + (size_t)i * DIM, out);
    }
}

// ---------------- fused angle-encoder + first A-conv edge pass ------------------
// h_ang[eid] is consumed only by edge eid of conv 0 -> compute it in place.
// Weight select between encoder sets is value-level (2x LDCU + FSEL), keeping
// the L1tex pipe free.
__global__ void __launch_bounds__(128, 6)
k_edge_enc(const float* __restrict__ x, float* __restrict__ e,
           const float* __restrict__ xa, const unsigned char* __restrict__ mask,
           const int* __restrict__ src, const int* __restrict__ dst, int n_edges,
           float* __restrict__ nd) {
    constexpr int W0 = 0;            // CG = 0
    constexpr int W1 = 256;
    constexpr int W2 = 512;
    constexpr int W4 = 1024;
    constexpr int B0 = 0;
    constexpr int LG = 32;
    constexpr int LB = 48;
    int eid = blockIdx.x * blockDim.x + threadIdx.x;
    if (eid >= n_edges) return;
    int s = src[eid], d = dst[eid];
    float xs[DIM], xd[DIM];
    load16(xs, x + (size_t)s * DIM);     // long-latency gathers issued first
    load16(xd, x + (size_t)d * DIM);
    // ---- inline angle encoder (overlaps gather latency) ----
    int mv = g_mask_mode ? ((const int*)mask)[eid] : (int)mask[eid];
    int m = mv ? 1 : 0;
    float ev[DIM];
    {
        float xval = xa[eid];
        float start = m ? -PI_F : 0.0f;
        float span  = m ? __fmul_rn(2.0f, PI_F) : PI_F;
        float step  = __fdividef(span, 15.0f);
        float gamma = __fdividef(1.0f, step);
        float feat[DIM];
#pragma unroll
        for (int j = 0; j < DIM; j++) {
            float cj = start + (float)j * step;
            float u  = gamma * (xval - cj);
            feat[j] = __expf(-(u * u));
        }
        float h[DIM];
#pragma unroll
        for (int j = 0; j < DIM; j++) h[j] = m ? c_eb1[16 + j] : c_eb1[j];
#pragma unroll
        for (int k = 0; k < DIM; k++) {
            float a = feat[k];
#pragma unroll
            for (int j = 0; j < DIM; j++) {
                float w = m ? c_ew1[256 + k * DIM + j] : c_ew1[k * DIM + j];
                h[j] = fmaf(a, w, h[j]);
            }
        }
#pragma unroll
        for (int j = 0; j < DIM; j++) h[j] = silu_f(h[j]);
#pragma unroll
        for (int j = 0; j < DIM; j++) ev[j] = m ? c_eb2[16 + j] : c_eb2[j];
#pragma unroll
        for (int k = 0; k < DIM; k++) {
            float a = h[k];
#pragma unroll
            for (int j = 0; j < DIM; j++) {
                float w = m ? c_ew2[256 + k * DIM + j] : c_ew2[k * DIM + j];
                ev[j] = fmaf(a, w, ev[j]);
            }
        }
        float lg[DIM], lb[DIM];
#pragma unroll
        for (int j = 0; j < DIM; j++) {
            lg[j] = m ? c_elg[16 + j] : c_elg[j];
            lb[j] = m ? c_elb[16 + j] : c_elb[j];
        }
        layernorm16(ev, lg, lb);
    }
    // ---- conv-edge body (CG = 0) ----
    float z[DIM];
#pragma unroll
    for (int j = 0; j < DIM; j++) z[j] = c_cb[B0 + j];
#pragma unroll
    for (int k = 0; k < DIM; k++) {
        float a = xs[k], b2 = xd[k], c = ev[k];
#pragma unroll
        for (int j = 0; j < DIM; j++) {
            z[j] = fmaf(a, c_cw[W0 + k * DIM + j], z[j]);
            z[j] = fmaf(b2, c_cw[W1 + k * DIM + j], z[j]);
            z[j] = fmaf(c, c_cw[W2 + k * DIM + j], z[j]);
        }
    }
    float msg[DIM];
#pragma unroll
    for (int j = 0; j < DIM; j++) msg[j] = 0.f;
#pragma unroll
    for (int k = 0; k < DIM; k++) {
        float a = xs[k];
#pragma unroll
        for (int j = 0; j < DIM; j++) msg[j] = fmaf(a, c_cw[W4 + k * DIM + j], msg[j]);
    }
    float* ndp = nd + (size_t)d * 32;
#pragma unroll
    for (int grp = 0; grp < 4; grp++) {
        float s0 = sigmoid_f(z[grp * 4 + 0]);
        float s1 = sigmoid_f(z[grp * 4 + 1]);
        float s2 = sigmoid_f(z[grp * 4 + 2]);
        float s3 = sigmoid_f(z[grp * 4 + 3]);
        red_add_v4(ndp + 16 + grp * 4, s0, s1, s2, s3);
        msg[grp * 4 + 0] *= s0;
        msg[grp * 4 + 1] *= s1;
        msg[grp * 4 + 2] *= s2;
        msg[grp * 4 + 3] *= s3;
        red_add_v4(ndp + grp * 4, msg[grp * 4 + 0], msg[grp * 4 + 1],
                                  msg[grp * 4 + 2], msg[grp * 4 + 3]);
    }
    // e_new = enc + silu(LN(z)); needed by conv 1's A-edge
    {
        float mu = 0.f;
#pragma unroll
        for (int j = 0; j < DIM; j++) mu += z[j];
        mu *= 0.0625f;
        float var = 0.f;
#pragma unroll
        for (int j = 0; j < DIM; j++) { float d0 = z[j] - mu; var = fmaf(d0, d0, var); }
        var *= 0.0625f;
        float r = __frsqrt_rn(var + 1e-5f);
#pragma unroll
        for (int j = 0; j < DIM; j++) {
            float t2 = fmaf((z[j] - mu) * r, c_cln[LG + j], c_cln[LB + j]);
            ev[j] += silu_f(t2);
        }
    }
    store16_cs(e + (size_t)eid * DIM, ev);
}

// ---------------- edge-gated conv: edge pass (constant weights) ----------------
template <int CG, bool STREAM_E, bool WRITE_E>
__global__ void __launch_bounds__(128, 7)
k_edge(const float* __restrict__ x, float* __restrict__ e,
       const int* __restrict__ src, const int* __restrict__ dst, int n_edges,
       float* __restrict__ nd) {
    constexpr int W0 = CG * 5 * 256;
    constexpr int W1 = W0 + 256;
    constexpr int W2 = W0 + 512;
    constexpr int W4 = W0 + 1024;
    constexpr int B0 = CG * 32;
    constexpr int LG = CG * 64 + 32;
    constexpr int LB = CG * 64 + 48;
    int eid = blockIdx.x * blockDim.x + threadIdx.x;
    if (eid >= n_edges) return;
    int s = src[eid], d = dst[eid];
    float xs[DIM], xd[DIM], ev[DIM];
    load16(xs, x + (size_t)s * DIM);
    load16(xd, x + (size_t)d * DIM);
    if (STREAM_E) load16_cs(ev, e + (size_t)eid * DIM);
    else          load16(ev, e + (size_t)eid * DIM);
    float z[DIM];
#pragma unroll
    for (int j = 0; j < DIM; j++) z[j] = c_cb[B0 + j];
#pragma unroll
    for (int k = 0; k < DIM; k++) {
        float a = xs[k], b2 = xd[k], c = ev[k];
#pragma unroll
        for (int j = 0; j < DIM; j++) {
            z[j] = fmaf(a, c_cw[W0 + k * DIM + j], z[j]);
            z[j] = fmaf(b2, c_cw[W1 + k * DIM + j], z[j]);
            z[j] = fmaf(c, c_cw[W2 + k * DIM + j], z[j]);
        }
    }
    float msg[DIM];
#pragma unroll
    for (int j = 0; j < DIM; j++) msg[j] = 0.f;
#pragma unroll
    for (int k = 0; k < DIM; k++) {
        float a = xs[k];
#pragma unroll
        for (int j = 0; j < DIM; j++) msg[j] = fmaf(a, c_cw[W4 + k * DIM + j], msg[j]);
    }
    float* ndp = nd + (size_t)d * 32;
#pragma unroll
    for (int grp = 0; grp < 4; grp++) {
        float s0 = sigmoid_f(z[grp * 4 + 0]);
        float s1 = sigmoid_f(z[grp * 4 + 1]);
        float s2 = sigmoid_f(z[grp * 4 + 2]);
        float s3 = sigmoid_f(z[grp * 4 + 3]);
        red_add_v4(ndp + 16 + grp * 4, s0, s1, s2, s3);
        msg[grp * 4 + 0] *= s0;
        msg[grp * 4 + 1] *= s1;
        msg[grp * 4 + 2] *= s2;
        msg[grp * 4 + 3] *= s3;
        red_add_v4(ndp + grp * 4, msg[grp * 4 + 0], msg[grp * 4 + 1],
                                  msg[grp * 4 + 2], msg[grp * 4 + 3]);
    }
    if (WRITE_E) {
        float mu = 0.f;
#pragma unroll
        for (int j = 0; j < DIM; j++) mu += z[j];
        mu *= 0.0625f;
        float var = 0.f;
#pragma unroll
        for (int j = 0; j < DIM; j++) { float d0 = z[j] - mu; var = fmaf(d0, d0, var); }
        var *= 0.0625f;
        float r = __frsqrt_rn(var + 1e-5f);
#pragma unroll
        for (int j = 0; j < DIM; j++) {
            float t2 = fmaf((z[j] - mu) * r, c_cln[LG + j], c_cln[LB + j]);
            ev[j] += silu_f(t2);
        }
        if (STREAM_E) store16_cs(e + (size_t)eid * DIM, ev);
        else          store16(e + (size_t)eid * DIM, ev);
    }
}

// ---------------- edge-gated conv: node pass (constant weights) ----------------
template <int CG, bool POOL>
__global__ void k_node(float* __restrict__ x, int n_nodes,
                       float* __restrict__ nd, const int* __restrict__ batch) {
    constexpr int W3 = CG * 5 * 256 + 768;
    constexpr int B1 = CG * 32 + 16;
    constexpr int LG = CG * 64;
    constexpr int LB = CG * 64 + 16;
    int i = blockIdx.x * blockDim.x + threadIdx.x;
    if (i >= n_nodes) return;
    float xv[DIM], h[DIM], nv[DIM], dv[DIM];
    load16(xv, x + (size_t)i * DIM);
    load16(nv, nd + (size_t)i * 32);
    load16(dv, nd + (size_t)i * 32 + 16);
    float zz[DIM];
#pragma unroll
    for (int j = 0; j < DIM; j++) zz[j] = 0.f;
    store16_cs(nd + (size_t)i * 32, zz);        // restore all-zero invariant
    store16_cs(nd + (size_t)i * 32 + 16, zz);
#pragma unroll
    for (int j = 0; j < DIM; j++) h[j] = 0.f;
#pragma unroll
    for (int k = 0; k < DIM; k++) {
        float a = xv[k];
#pragma unroll
        for (int j = 0; j < DIM; j++) h[j] = fmaf(a, c_cw[W3 + k * DIM + j], h[j]);
    }
#pragma unroll
    for (int j = 0; j < DIM; j++)
        h[j] = h[j] + c_cb[B1 + j] + __fdividef(nv[j], dv[j] + 1e-5f);
    {
        float mu = 0.f;
#pragma unroll
        for (int j = 0; j < DIM; j++) mu += h[j];
        mu *= 0.0625f;
        float var = 0.f;
#pragma unroll
        for (int j = 0; j < DIM; j++) { float d0 = h[j] - mu; var = fmaf(d0, d0, var); }
        var *= 0.0625f;
        float r = __frsqrt_rn(var + 1e-5f);
#pragma unroll
        for (int j = 0; j < DIM; j++) {
            float t2 = fmaf((h[j] - mu) * r, c_cln[LG + j], c_cln[LB + j]);
            xv[j] += silu_f(t2);
        }
    }
    store16(x + (size_t)i * DIM, xv);
    if (POOL) {
        int g = batch[i];
        float* p = g_pool + g * DIM;
        red_add_v4(p + 0, xv[0], xv[1], xv[2], xv[3]);
        red_add_v4(p + 4, xv[4], xv[5], xv[6], xv[7]);
        red_add_v4(p + 8, xv[8], xv[9], xv[10], xv[11]);
        red_add_v4(p + 12, xv[12], xv[13], xv[14], xv[15]);
    }
}

// ---------------- head ----------------------------------------------------------
__global__ void k_head(const float* __restrict__ fp,
                       const float* __restrict__ l1W, const float* __restrict__ l1b,
                       const float* __restrict__ l2W, const float* __restrict__ l2b,
                       float* __restrict__ out) {
    __shared__ float sW[288], sb1h[16], sW2h[16];
    int t = threadIdx.x;
    for (int i = t; i < 288; i += blockDim.x) sW[i] = l1W[i];
    if (t < 16) { sb1h[t] = l1b[t]; sW2h[t] = l2W[t]; }
    __syncthreads();
    int g = t;  // blockDim = 256 = NGRAPH
    float xin[18];
#pragma unroll
    for (int j = 0; j < DIM; j++) xin[j] = g_pool[g * DIM + j];
    xin[16] = fp[2 * g];
    xin[17] = fp[2 * g + 1];
    float zz[DIM];
#pragma unroll
    for (int j = 0; j < DIM; j++) zz[j] = 0.f;
    store16(g_pool + g * DIM, zz);   // restore invariant
    float acc = 0.f;
#pragma unroll
    for (int d = 0; d < DIM; d++) {
        float tv = 0.f;
#pragma unroll
        for (int j = 0; j < 18; j++) tv = fmaf(xin[j], sW[j * DIM + d], tv);
        tv += sb1h[d];
        tv = (tv >= 0.f) ? tv : 0.01f * tv;
        acc = fmaf(tv, sW2h[d], acc);
    }
    out[g] = acc + l2b[0];
}

// ---------------- host ----------------------------------------------------------
extern "C" void kernel_launch(void* const* d_in, const int* in_sizes, int n_in,
                              void* d_out, int out_size) {
    const int* x_atm            = (const int*)d_in[0];
    const float* x_bnd          = (const float*)d_in[1];
    const float* x_ang          = (const float*)d_in[2];
    const unsigned char* mask   = (const unsigned char*)d_in[3];
    const int* eG               = (const int*)d_in[4];
    const int* eA               = (const int*)d_in[5];
    const int* batch            = (const int*)d_in[6];
    const float* fp             = (const float*)d_in[7];
    const float* enc_W1         = (const float*)d_in[8];
    const float* enc_b1         = (const float*)d_in[9];
    const float* enc_W2         = (const float*)d_in[10];
    const float* enc_b2         = (const float*)d_in[11];
    const float* enc_g          = (const float*)d_in[12];
    const float* enc_bb         = (const float*)d_in[13];
    const float* conv_W         = (const float*)d_in[14];
    const float* conv_b         = (const float*)d_in[15];
    const float* conv_ln        = (const float*)d_in[16];
    const float* l1W            = (const float*)d_in[17];
    const float* l1b            = (const float*)d_in[18];
    const float* l2W            = (const float*)d_in[19];
    const float* l2b            = (const float*)d_in[20];
    float* out = (float*)d_out;

    float *h_atm, *h_bnd, *h_ang, *nd;
    cudaGetSymbolAddress((void**)&h_atm, g_h_atm);
    cudaGetSymbolAddress((void**)&h_bnd, g_h_bnd);
    cudaGetSymbolAddress((void**)&h_ang, g_h_ang);
    cudaGetSymbolAddress((void**)&nd, g_nd);

    const int B = 256;
    const int BE = 128;

    // ---- stage conv + angle-encoder params into constant memory (D2D) ----
    cudaMemcpyToSymbolAsync(c_cw, conv_W, sizeof(c_cw), 0, cudaMemcpyDeviceToDevice);
    cudaMemcpyToSymbolAsync(c_cb, conv_b, sizeof(c_cb), 0, cudaMemcpyDeviceToDevice);
    cudaMemcpyToSymbolAsync(c_cln, conv_ln, sizeof(c_cln), 0, cudaMemcpyDeviceToDevice);
    cudaMemcpyToSymbolAsync(c_ew1, enc_W1 + 512, sizeof(c_ew1), 0, cudaMemcpyDeviceToDevice);
    cudaMemcpyToSymbolAsync(c_ew2, enc_W2 + 512, sizeof(c_ew2), 0, cudaMemcpyDeviceToDevice);
    cudaMemcpyToSymbolAsync(c_eb1, enc_b1 + 32, sizeof(c_eb1), 0, cudaMemcpyDeviceToDevice);
    cudaMemcpyToSymbolAsync(c_eb2, enc_b2 + 32, sizeof(c_eb2), 0, cudaMemcpyDeviceToDevice);
    cudaMemcpyToSymbolAsync(c_elg, enc_g + 32, sizeof(c_elg), 0, cudaMemcpyDeviceToDevice);
    cudaMemcpyToSymbolAsync(c_elb, enc_bb + 32, sizeof(c_elb), 0, cudaMemcpyDeviceToDevice);

    // ---- encoder (atoms + bonds; angle encoder fused into first A-edge) ----
    k_detect_mask<<<1, 256>>>(mask);
    k_enc_nb<<<ATM_BLOCKS + BND_BLOCKS, B>>>(x_atm, x_bnd,
                                             enc_W1, enc_b1, enc_W2, enc_b2, enc_g, enc_bb);

    // ---- processor: 3 x (A conv then G conv); nd zeroed by node passes ----
    // c = 0 (A-edge fused with angle encoder)
    k_edge_enc<<<NANG / BE, BE>>>(h_bnd, h_ang, x_ang, mask, eA, eA + NANG, NANG, nd);
    k_node<0, false><<<NB / B, B>>>(h_bnd, NB, nd, nullptr);
    k_edge<1, false, true><<<NB / BE, BE>>>(h_atm, h_bnd, eG, eG + NB, NB, nd);
    k_node<1, false><<<NA / B, B>>>(h_atm, NA, nd, nullptr);
    // c = 1
    k_edge<2, true, true><<<NANG / BE, BE>>>(h_bnd, h_ang, eA, eA + NANG, NANG, nd);
    k_node<2, false><<<NB / B, B>>>(h_bnd, NB, nd, nullptr);
    k_edge<3, false, true><<<NB / BE, BE>>>(h_atm, h_bnd, eG, eG + NB, NB, nd);
    k_node<3, false><<<NA / B, B>>>(h_atm, NA, nd, nullptr);
    // c = 2 (dead e-stores eliminated)
    k_edge<4, true, false><<<NANG / BE, BE>>>(h_bnd, h_ang, eA, eA + NANG, NANG, nd);
    k_node<4, false><<<NB / B, B>>>(h_bnd, NB, nd, nullptr);
    k_edge<5, false, false><<<NB / BE, BE>>>(h_atm, h_bnd, eG, eG + NB, NB, nd);
    k_node<5, true><<<NA / B, B>>>(h_atm, NA, nd, batch);   // fused pool

    // ---- head (pool zeroed by head) ----
    k_head<<<1, 256>>>(fp, l1W, l1b, l2W, l2b, out);
}

// round 14
// speedup vs baseline: 1.1208x; 1.1208x over previous
#include <cuda_runtime.h>
#include <math.h>
#include <stdint.h>

#define DIM 16
#define NA 131072
#define NB 1048576
#define NANG 2097152
#define NGRAPH 256
#define PI_F 3.14159274101257324219f   // fl32(pi)
#define CUTOFF_F 5.0f

// ---------------- scratch (static device globals; no runtime alloc) ----------
// Invariant: g_nd and g_pool are all-zero at entry; restored before exit.
__device__ float g_h_atm[NA * DIM];
__device__ float g_h_bnd[NB * DIM];
__device__ float g_h_ang[NANG * DIM];
__device__ float g_nd[NB * 32];       // per node: [num(16) | den(16)] = one 128B line
__device__ float g_pool[NGRAPH * DIM];
__device__ int   g_mask_mode;         // 1 = mask serialized as int32, 0 = as bytes

// ---------------- conv parameters in constant memory --------------------------
// (warp-uniform access only -> LDCU path)
__constant__ float c_cw[3 * 2 * 5 * 256];      // conv_W  [c][g][5][16][16]
__constant__ float c_cb[3 * 2 * 2 * 16];       // conv_b  [c][g][2][16]
__constant__ float c_cln[3 * 2 * 2 * 2 * 16];  // conv_ln [c][g][2][2][16]

// ---------------- fast activations ---------------------------------------------
__device__ __forceinline__ float sigmoid_f(float x) {
    return __fdividef(1.0f, 1.0f + __expf(-x));
}
__device__ __forceinline__ float silu_f(float x) { return x * sigmoid_f(x); }

// ---------------- accurate sinf (FMA Cody-Waite) -------------------------------
__device__ __forceinline__ float sinf_cw(float x) {
    float k = rintf(__fmul_rn(x, 0.636619772367581343f));
    float r = fmaf(k, -1.57079637050628662109375f, x);
    r = fmaf(k, 4.37113900018624283e-8f, r);
    int q = ((int)k) & 3;
    float s = __fmul_rn(r, r);
    float ps = 2.75573192239859e-6f;
    ps = fmaf(ps, s, -1.98412698412698e-4f);
    ps = fmaf(ps, s, 8.33333333333333e-3f);
    ps = fmaf(ps, s, -1.66666666666667e-1f);
    float sinr = fmaf(__fmul_rn(r, s), ps, r);
    float pc = 2.48015873015873e-5f;
    pc = fmaf(pc, s, -1.38888888888889e-3f);
    pc = fmaf(pc, s, 4.16666666666667e-2f);
    pc = fmaf(pc, s, -5.0e-1f);
    float cosr = fmaf(s, pc, 1.0f);
    float v = (q & 1) ? cosr : sinr;
    return (q & 2) ? -v : v;
}

// ---------------- misc helpers -------------------------------------------------
__device__ __forceinline__ void red_add_v4(float* p, float a, float b, float c, float d) {
    asm volatile("red.global.add.v4.f32 [%0], {%1,%2,%3,%4};"
                 :: "l"(p), "f"(a), "f"(b), "f"(c), "f"(d) : "memory");
}
__device__ __forceinline__ void load16(float* r, const float* p) {
#pragma unroll
    for (int i = 0; i < 4; i++) {
        float4 v = ((const float4*)p)[i];
        r[4 * i + 0] = v.x; r[4 * i + 1] = v.y; r[4 * i + 2] = v.z; r[4 * i + 3] = v.w;
    }
}
__device__ __forceinline__ void load16_cs(float* r, const float* p) {
#pragma unroll
    for (int i = 0; i < 4; i++) {
        float4 v = __ldcs((const float4*)p + i);
        r[4 * i + 0] = v.x; r[4 * i + 1] = v.y; r[4 * i + 2] = v.z; r[4 * i + 3] = v.w;
    }
}
__device__ __forceinline__ void store16(float* p, const float* r) {
#pragma unroll
    for (int i = 0; i < 4; i++)
        ((float4*)p)[i] = make_float4(r[4 * i + 0], r[4 * i + 1], r[4 * i + 2], r[4 * i + 3]);
}
__device__ __forceinline__ void store16_cs(float* p, const float* r) {
#pragma unroll
    for (int i = 0; i < 4; i++)
        __stcs((float4*)p + i, make_float4(r[4 * i + 0], r[4 * i + 1], r[4 * i + 2], r[4 * i + 3]));
}

__device__ __forceinline__ void layernorm16(float* v, const float* g, const float* b) {
    float mu = 0.f;
#pragma unroll
    for (int j = 0; j < DIM; j++) mu += v[j];
    mu *= 0.0625f;
    float var = 0.f;
#pragma unroll
    for (int j = 0; j < DIM; j++) { float d0 = v[j] - mu; var = fmaf(d0, d0, var); }
    var *= 0.0625f;
    float r = __frsqrt_rn(var + 1e-5f);
#pragma unroll
    for (int j = 0; j < DIM; j++) v[j] = fmaf((v[j] - mu) * r, g[j], b[j]);
}

__device__ __forceinline__ void embed_16(const float* feat, float* out,
                                         const float* sW1, const float* sb1,
                                         const float* sW2, const float* sb2,
                                         const float* sg, const float* sb) {
    float h[DIM], o[DIM];
#pragma unroll
    for (int j = 0; j < DIM; j++) h[j] = sb1[j];
#pragma unroll
    for (int k = 0; k < DIM; k++) {
        float a = feat[k];
#pragma unroll
        for (int j = 0; j < DIM; j++) h[j] = fmaf(a, sW1[k * DIM + j], h[j]);
    }
#pragma unroll
    for (int j = 0; j < DIM; j++) h[j] = silu_f(h[j]);
#pragma unroll
    for (int j = 0; j < DIM; j++) o[j] = sb2[j];
#pragma unroll
    for (int k = 0; k < DIM; k++) {
        float a = h[k];
#pragma unroll
        for (int j = 0; j < DIM; j++) o[j] = fmaf(a, sW2[k * DIM + j], o[j]);
    }
    layernorm16(o, sg, sb);
#pragma unroll
    for (int j = 0; j < DIM; j++) out[j] = o[j];
}

// ---------------- mask-layout detection ----------------------------------------
__global__ void k_detect_mask(const unsigned char* __restrict__ m) {
    __shared__ int s_nz;
    if (threadIdx.x == 0) s_nz = 0;
    __syncthreads();
    int nz = 0;
    for (int i = threadIdx.x; i < 65536; i += blockDim.x)
        if ((i & 3) && m[i]) nz = 1;
    if (nz) atomicOr(&s_nz, 1);
    __syncthreads();
    if (threadIdx.x == 0) g_mask_mode = s_nz ? 0 : 1;
}

// ---------------- fused encoder: atoms (+table) and bonds ----------------------
#define ATM_BLOCKS (NA / 256)
#define BND_BLOCKS (NB / 256)
__global__ void k_enc_nb(const int* __restrict__ species, const float* __restrict__ xb,
                         const float* __restrict__ eW1, const float* __restrict__ eb1,
                         const float* __restrict__ eW2, const float* __restrict__ eb2,
                         const float* __restrict__ eg, const float* __restrict__ ebb) {
    int b = blockIdx.x;
    int t = threadIdx.x;
    if (b < ATM_BLOCKS) {
        __shared__ float s_tab[10 * DIM];
        if (t < 10) {
            int s = t;
            float h[DIM], o[DIM];
#pragma unroll
            for (int d = 0; d < DIM; d++) h[d] = silu_f(eW1[s * DIM + d] + eb1[d]);
#pragma unroll
            for (int j = 0; j < DIM; j++) o[j] = eb2[j];
#pragma unroll
            for (int k = 0; k < DIM; k++) {
                float a = h[k];
#pragma unroll
                for (int j = 0; j < DIM; j++) o[j] = fmaf(a, eW2[k * DIM + j], o[j]);
            }
            float g[DIM], bb2[DIM];
#pragma unroll
            for (int j = 0; j < DIM; j++) { g[j] = eg[j]; bb2[j] = ebb[j]; }
            layernorm16(o, g, bb2);
#pragma unroll
            for (int j = 0; j < DIM; j++) s_tab[s * DIM + j] = o[j];
        }
        __syncthreads();
        int i = b * 256 + t;
        int s = species[i];
        float4* dst = (float4*)(g_h_atm + (size_t)i * DIM);
        const float4* srcp = (const float4*)(s_tab + s * DIM);
#pragma unroll
        for (int q = 0; q < 4; q++) dst[q] = srcp[q];
    } else {
        __shared__ float sW1[256], sW2[256], sb1[16], sb2[16], sg[16], sb[16];
        for (int i = t; i < 256; i += blockDim.x) {
            sW1[i] = eW1[256 + i];
            sW2[i] = eW2[256 + i];
        }
        if (t < 16) {
            sb1[t] = eb1[16 + t]; sb2[t] = eb2[16 + t];
            sg[t] = eg[16 + t];   sb[t] = ebb[16 + t];
        }
        __syncthreads();
        int i = (b - ATM_BLOCKS) * 256 + t;
        float xx = xb[i] + 1e-5f;
        float c0 = __fdividef(0.6324555320336759f, xx);
        float feat[DIM];
#pragma unroll
        for (int j = 0; j < DIM; j++) {
            float arg = __fmul_rn(__fmul_rn((float)(j + 1), PI_F), xx) * 0.2f;
            feat[j] = c0 * sinf_cw(arg);
        }
        float out[DIM];
        embed_16(feat, out, sW1, sb1, sW2, sb2, sg, sb);
        store16_cs(g_h_bnd + (size_t)i * DIM, out);
    }
}

// ---------------- angle encoder (gaussian basis, smem weights) -----------------
__global__ void k_enc_ang(const float* __restrict__ xa, const unsigned char* __restrict__ mask, int n,
                          const float* __restrict__ encW1, const float* __restrict__ encb1,
                          const float* __restrict__ encW2, const float* __restrict__ encb2,
                          const float* __restrict__ encg, const float* __restrict__ encb) {
    __shared__ float sW1[2][256], sW2[2][256], sb1[2][16], sb2[2][16], sg[2][16], sb[2][16];
    int t = threadIdx.x;
    for (int i = t; i < 512; i += blockDim.x) {
        int m = i / 256, j = i % 256;
        sW1[m][j] = encW1[(2 + m) * 256 + j];
        sW2[m][j] = encW2[(2 + m) * 256 + j];
    }
    if (t < 32) {
        int m = t / 16, j = t % 16;
        sb1[m][j] = encb1[(2 + m) * 16 + j];
        sb2[m][j] = encb2[(2 + m) * 16 + j];
        sg[m][j]  = encg[(2 + m) * 16 + j];
        sb[m][j]  = encb[(2 + m) * 16 + j];
    }
    __syncthreads();
    int i = blockIdx.x * blockDim.x + t;
    if (i >= n) return;
    int mv = g_mask_mode ? ((const int*)mask)[i] : (int)mask[i];
    int m = mv ? 1 : 0;
    float x = xa[i];
    float start = m ? -PI_F : 0.0f;
    float span  = m ? __fmul_rn(2.0f, PI_F) : PI_F;
    float step  = __fdividef(span, 15.0f);
    float gamma = __fdividef(1.0f, step);
    float feat[DIM];
#pragma unroll
    for (int j = 0; j < DIM; j++) {
        float cj = start + (float)j * step;
        float u  = gamma * (x - cj);
        feat[j] = __expf(-(u * u));
    }
    float out[DIM];
    embed_16(feat, out, sW1[m], sb1[m], sW2[m], sb2[m], sg[m], sb[m]);
    store16_cs(g_h_ang + (size_t)i * DIM, out);
}

// ---------------- edge-gated conv: edge pass (constant weights) ----------------
// WRITE_E=false: conv-2 edge passes skip the never-read e update entirely.
template <int CG, bool STREAM_E, bool WRITE_E>
__global__ void __launch_bounds__(128, 7)
k_edge(const float* __restrict__ x, float* __restrict__ e,
       const int* __restrict__ src, const int* __restrict__ dst, int n_edges,
       float* __restrict__ nd) {
    constexpr int W0 = CG * 5 * 256;
    constexpr int W1 = W0 + 256;
    constexpr int W2 = W0 + 512;
    constexpr int W4 = W0 + 1024;
    constexpr int B0 = CG * 32;
    constexpr int LG = CG * 64 + 32;
    constexpr int LB = CG * 64 + 48;
    int eid = blockIdx.x * blockDim.x + threadIdx.x;
    if (eid >= n_edges) return;
    int s = src[eid], d = dst[eid];
    float xs[DIM], xd[DIM], ev[DIM];
    load16(xs, x + (size_t)s * DIM);
    load16(xd, x + (size_t)d * DIM);
    if (STREAM_E) load16_cs(ev, e + (size_t)eid * DIM);
    else          load16(ev, e + (size_t)eid * DIM);
    float z[DIM];
#pragma unroll
    for (int j = 0; j < DIM; j++) z[j] = c_cb[B0 + j];
#pragma unroll
    for (int k = 0; k < DIM; k++) {
        float a = xs[k], b2 = xd[k], c = ev[k];
#pragma unroll
        for (int j = 0; j < DIM; j++) {
            z[j] = fmaf(a, c_cw[W0 + k * DIM + j], z[j]);
            z[j] = fmaf(b2, c_cw[W1 + k * DIM + j], z[j]);
            z[j] = fmaf(c, c_cw[W2 + k * DIM + j], z[j]);
        }
    }
    float msg[DIM];
#pragma unroll
    for (int j = 0; j < DIM; j++) msg[j] = 0.f;
#pragma unroll
    for (int k = 0; k < DIM; k++) {
        float a = xs[k];
#pragma unroll
        for (int j = 0; j < DIM; j++) msg[j] = fmaf(a, c_cw[W4 + k * DIM + j], msg[j]);
    }
    float* ndp = nd + (size_t)d * 32;
#pragma unroll
    for (int grp = 0; grp < 4; grp++) {
        float s0 = sigmoid_f(z[grp * 4 + 0]);
        float s1 = sigmoid_f(z[grp * 4 + 1]);
        float s2 = sigmoid_f(z[grp * 4 + 2]);
        float s3 = sigmoid_f(z[grp * 4 + 3]);
        red_add_v4(ndp + 16 + grp * 4, s0, s1, s2, s3);   // den
        msg[grp * 4 + 0] *= s0;
        msg[grp * 4 + 1] *= s1;
        msg[grp * 4 + 2] *= s2;
        msg[grp * 4 + 3] *= s3;
        red_add_v4(ndp + grp * 4, msg[grp * 4 + 0], msg[grp * 4 + 1],
                                  msg[grp * 4 + 2], msg[grp * 4 + 3]);  // num
    }
    if (WRITE_E) {
        float mu = 0.f;
#pragma unroll
        for (int j = 0; j < DIM; j++) mu += z[j];
        mu *= 0.0625f;
        float var = 0.f;
#pragma unroll
        for (int j = 0; j < DIM; j++) { float d0 = z[j] - mu; var = fmaf(d0, d0, var); }
        var *= 0.0625f;
        float r = __frsqrt_rn(var + 1e-5f);
#pragma unroll
        for (int j = 0; j < DIM; j++) {
            float t2 = fmaf((z[j] - mu) * r, c_cln[LG + j], c_cln[LB + j]);
            ev[j] += silu_f(t2);
        }
        if (STREAM_E) store16_cs(e + (size_t)eid * DIM, ev);
        else          store16(e + (size_t)eid * DIM, ev);
    }
}

// ---------------- edge-gated conv: node pass (constant weights) ----------------
template <int CG, bool POOL>
__global__ void k_node(float* __restrict__ x, int n_nodes,
                       float* __restrict__ nd, const int* __restrict__ batch) {
    constexpr int W3 = CG * 5 * 256 + 768;
    constexpr int B1 = CG * 32 + 16;
    constexpr int LG = CG * 64;
    constexpr int LB = CG * 64 + 16;
    int i = blockIdx.x * blockDim.x + threadIdx.x;
    if (i >= n_nodes) return;
    float xv[DIM], h[DIM], nv[DIM], dv[DIM];
    load16(xv, x + (size_t)i * DIM);
    load16(nv, nd + (size_t)i * 32);
    load16(dv, nd + (size_t)i * 32 + 16);
    float zz[DIM];
#pragma unroll
    for (int j = 0; j < DIM; j++) zz[j] = 0.f;
    store16_cs(nd + (size_t)i * 32, zz);        // restore all-zero invariant
    store16_cs(nd + (size_t)i * 32 + 16, zz);
#pragma unroll
    for (int j = 0; j < DIM; j++) h[j] = 0.f;
#pragma unroll
    for (int k = 0; k < DIM; k++) {
        float a = xv[k];
#pragma unroll
        for (int j = 0; j < DIM; j++) h[j] = fmaf(a, c_cw[W3 + k * DIM + j], h[j]);
    }
#pragma unroll
    for (int j = 0; j < DIM; j++)
        h[j] = h[j] + c_cb[B1 + j] + __fdividef(nv[j], dv[j] + 1e-5f);
    {
        float mu = 0.f;
#pragma unroll
        for (int j = 0; j < DIM; j++) mu += h[j];
        mu *= 0.0625f;
        float var = 0.f;
#pragma unroll
        for (int j = 0; j < DIM; j++) { float d0 = h[j] - mu; var = fmaf(d0, d0, var); }
        var *= 0.0625f;
        float r = __frsqrt_rn(var + 1e-5f);
#pragma unroll
        for (int j = 0; j < DIM; j++) {
            float t2 = fmaf((h[j] - mu) * r, c_cln[LG + j], c_cln[LB + j]);
            xv[j] += silu_f(t2);
        }
    }
    store16(x + (size_t)i * DIM, xv);
    if (POOL) {
        int g = batch[i];
        float* p = g_pool + g * DIM;
        red_add_v4(p + 0, xv[0], xv[1], xv[2], xv[3]);
        red_add_v4(p + 4, xv[4], xv[5], xv[6], xv[7]);
        red_add_v4(p + 8, xv[8], xv[9], xv[10], xv[11]);
        red_add_v4(p + 12, xv[12], xv[13], xv[14], xv[15]);
    }
}

// ---------------- head ----------------------------------------------------------
__global__ void k_head(const float* __restrict__ fp,
                       const float* __restrict__ l1W, const float* __restrict__ l1b,
                       const float* __restrict__ l2W, const float* __restrict__ l2b,
                       float* __restrict__ out) {
    __shared__ float sW[288], sb1h[16], sW2h[16];
    int t = threadIdx.x;
    for (int i = t; i < 288; i += blockDim.x) sW[i] = l1W[i];
    if (t < 16) { sb1h[t] = l1b[t]; sW2h[t] = l2W[t]; }
    __syncthreads();
    int g = t;  // blockDim = 256 = NGRAPH
    float xin[18];
#pragma unroll
    for (int j = 0; j < DIM; j++) xin[j] = g_pool[g * DIM + j];
    xin[16] = fp[2 * g];
    xin[17] = fp[2 * g + 1];
    float zz[DIM];
#pragma unroll
    for (int j = 0; j < DIM; j++) zz[j] = 0.f;
    store16(g_pool + g * DIM, zz);   // restore invariant
    float acc = 0.f;
#pragma unroll
    for (int d = 0; d < DIM; d++) {
        float tv = 0.f;
#pragma unroll
        for (int j = 0; j < 18; j++) tv = fmaf(xin[j], sW[j * DIM + d], tv);
        tv += sb1h[d];
        tv = (tv >= 0.f) ? tv : 0.01f * tv;
        acc = fmaf(tv, sW2h[d], acc);
    }
    out[g] = acc + l2b[0];
}

// ---------------- host ----------------------------------------------------------
extern "C" void kernel_launch(void* const* d_in, const int* in_sizes, int n_in,
                              void* d_out, int out_size) {
    const int* x_atm            = (const int*)d_in[0];
    const float* x_bnd          = (const float*)d_in[1];
    const float* x_ang          = (const float*)d_in[2];
    const unsigned char* mask   = (const unsigned char*)d_in[3];
    const int* eG               = (const int*)d_in[4];
    const int* eA               = (const int*)d_in[5];
    const int* batch            = (const int*)d_in[6];
    const float* fp             = (const float*)d_in[7];
    const float* enc_W1         = (const float*)d_in[8];
    const float* enc_b1         = (const float*)d_in[9];
    const float* enc_W2         = (const float*)d_in[10];
    const float* enc_b2         = (const float*)d_in[11];
    const float* enc_g          = (const float*)d_in[12];
    const float* enc_bb         = (const float*)d_in[13];
    const float* conv_W         = (const float*)d_in[14];
    const float* conv_b         = (const float*)d_in[15];
    const float* conv_ln        = (const float*)d_in[16];
    const float* l1W            = (const float*)d_in[17];
    const float* l1b            = (const float*)d_in[18];
    const float* l2W            = (const float*)d_in[19];
    const float* l2b            = (const float*)d_in[20];
    float* out = (float*)d_out;

    float *h_atm, *h_bnd, *h_ang, *nd;
    cudaGetSymbolAddress((void**)&h_atm, g_h_atm);
    cudaGetSymbolAddress((void**)&h_bnd, g_h_bnd);
    cudaGetSymbolAddress((void**)&h_ang, g_h_ang);
    cudaGetSymbolAddress((void**)&nd, g_nd);

    const int B = 256;
    const int BE = 128;

    // ---- stage conv params into constant memory (D2D async, capturable) ----
    cudaMemcpyToSymbolAsync(c_cw, conv_W, sizeof(c_cw), 0, cudaMemcpyDeviceToDevice);
    cudaMemcpyToSymbolAsync(c_cb, conv_b, sizeof(c_cb), 0, cudaMemcpyDeviceToDevice);
    cudaMemcpyToSymbolAsync(c_cln, conv_ln, sizeof(c_cln), 0, cudaMemcpyDeviceToDevice);

    // ---- encoder ----
    k_detect_mask<<<1, 256>>>(mask);
    k_enc_nb<<<ATM_BLOCKS + BND_BLOCKS, B>>>(x_atm, x_bnd,
                                             enc_W1, enc_b1, enc_W2, enc_b2, enc_g, enc_bb);
    k_enc_ang<<<NANG / B, B>>>(x_ang, mask, NANG, enc_W1, enc_b1, enc_W2, enc_b2, enc_g, enc_bb);

    // ---- processor: 3 x (A conv then G conv); nd zeroed by node passes ----
    // c = 0
    k_edge<0, true, true><<<NANG / BE, BE>>>(h_bnd, h_ang, eA, eA + NANG, NANG, nd);
    k_node<0, false><<<NB / B, B>>>(h_bnd, NB, nd, nullptr);
    k_edge<1, false, true><<<NB / BE, BE>>>(h_atm, h_bnd, eG, eG + NB, NB, nd);
    k_node<1, false><<<NA / B, B>>>(h_atm, NA, nd, nullptr);
    // c = 1
    k_edge<2, true, true><<<NANG / BE, BE>>>(h_bnd, h_ang, eA, eA + NANG, NANG, nd);
    k_node<2, false><<<NB / B, B>>>(h_bnd, NB, nd, nullptr);
    k_edge<3, false, true><<<NB / BE, BE>>>(h_atm, h_bnd, eG, eG + NB, NB, nd);
    k_node<3, false><<<NA / B, B>>>(h_atm, NA, nd, nullptr);
    // c = 2 (dead e-stores eliminated: h_ang and h_bnd-as-edge never read again)
    k_edge<4, true, false><<<NANG / BE, BE>>>(h_bnd, h_ang, eA, eA + NANG, NANG, nd);
    k_node<4, false><<<NB / B, B>>>(h_bnd, NB, nd, nullptr);
    k_edge<5, false, false><<<NB / BE, BE>>>(h_atm, h_bnd, eG, eG + NB, NB, nd);
    k_node<5, true><<<NA / B, B>>>(h_atm, NA, nd, batch);   // fused pool

    // ---- head (pool zeroed by head) ----
    k_head<<<1, 256>>>(fp, l1W, l1b, l2W, l2b, out);
}